// round 11
// baseline (speedup 1.0000x reference)
#include <cuda_runtime.h>
#include <cuda_fp16.h>
#include <cstdint>

#define DOUT 1024
#define NROWS 8192
#define NCAP 10
#define KDIM 1024

// ---------------- scratch (device globals: allocation-rule-safe) ----------
__device__ float2 g_cs[NCAP * 512];
__device__ __half g_Ux[(size_t)NROWS * 3072];
__device__ __half g_SR[(size_t)NROWS * 1024];
__device__ __half g_SG[(size_t)NROWS * 1024];
__device__ __half g_xh[(size_t)NROWS * 1024];
__device__ __half g_sh[(size_t)NROWS * 1024];
__device__ __half g_Uh[(size_t)1024 * 3072];
__device__ __half g_Wrh[(size_t)1024 * 1024];
__device__ __half g_Wgh[(size_t)1024 * 1024];

// ---------------- helpers ---------------------------------------------------
__device__ __forceinline__ uint32_t smem_u32(const void* p) {
    uint32_t a;
    asm("{ .reg .u64 t; cvta.to.shared.u64 t, %1; cvt.u32.u64 %0, t; }" : "=r"(a) : "l"(p));
    return a;
}
__device__ __forceinline__ void cp16(uint32_t s, const void* g) {
    asm volatile("cp.async.cg.shared.global [%0], [%1], 16;" :: "r"(s), "l"(g));
}
#define CP_COMMIT() asm volatile("cp.async.commit_group;" ::: "memory")
#define CP_WAIT(n)  asm volatile("cp.async.wait_group %0;" :: "n"(n) : "memory")

__device__ __forceinline__ void ldsm_x4(uint32_t* r, uint32_t addr) {
    asm volatile("ldmatrix.sync.aligned.m8n8.x4.shared.b16 {%0,%1,%2,%3}, [%4];"
                 : "=r"(r[0]), "=r"(r[1]), "=r"(r[2]), "=r"(r[3]) : "r"(addr));
}
__device__ __forceinline__ void ldsm_x4_t(uint32_t* r, uint32_t addr) {
    asm volatile("ldmatrix.sync.aligned.m8n8.x4.trans.shared.b16 {%0,%1,%2,%3}, [%4];"
                 : "=r"(r[0]), "=r"(r[1]), "=r"(r[2]), "=r"(r[3]) : "r"(addr));
}
__device__ __forceinline__ void mma_f16(float* d, const uint32_t* a, const uint32_t* b) {
    asm volatile(
        "mma.sync.aligned.m16n8k16.row.col.f32.f16.f16.f32 "
        "{%0,%1,%2,%3}, {%4,%5,%6,%7}, {%8,%9}, {%0,%1,%2,%3};"
        : "+f"(d[0]), "+f"(d[1]), "+f"(d[2]), "+f"(d[3])
        : "r"(a[0]), "r"(a[1]), "r"(a[2]), "r"(a[3]), "r"(b[0]), "r"(b[1]));
}

// ---------------- trig table (packed cos/sin) ------------------------------
__global__ void trig_kernel(const float* __restrict__ theta) {
    int i = blockIdx.x, a = threadIdx.x;
    float s, c;
    sincosf(theta[i * 512 + a], &s, &c);
    g_cs[i * 512 + a] = make_float2(c, s);
}

// ---------------- fp32 -> fp16 convert (x, state, U, Wr, Wg) ---------------
__global__ __launch_bounds__(256) void f2h_all(const float* __restrict__ x,
                                               const float* __restrict__ state,
                                               const float* __restrict__ U,
                                               const float* __restrict__ Wr,
                                               const float* __restrict__ Wg) {
    const float* in; __half* out; int n4;
    switch (blockIdx.y) {
        case 0: in = x;     out = g_xh;  n4 = NROWS * 1024 / 4; break;
        case 1: in = state; out = g_sh;  n4 = NROWS * 1024 / 4; break;
        case 2: in = U;     out = g_Uh;  n4 = 1024 * 3072 / 4;  break;
        case 3: in = Wr;    out = g_Wrh; n4 = 1024 * 1024 / 4;  break;
        default: in = Wg;   out = g_Wgh; n4 = 1024 * 1024 / 4;  break;
    }
    int i = blockIdx.x * 256 + threadIdx.x;
    int stride = gridDim.x * 256;
    for (; i < n4; i += stride) {
        float4 v = reinterpret_cast<const float4*>(in)[i];
        __half2 h0 = __floats2half2_rn(v.x, v.y);
        __half2 h1 = __floats2half2_rn(v.z, v.w);
        uint2 u;
        u.x = *reinterpret_cast<const uint32_t*>(&h0);
        u.y = *reinterpret_cast<const uint32_t*>(&h1);
        reinterpret_cast<uint2*>(out)[i] = u;
    }
}

// ---------------- mma.sync fp16 GEMM (fp16 output) --------------------------
// C[M,N] = A[M,K] * B[K,N]. BM=128, BN=256, BK=32, 8 warps, warp tile 64x64.
constexpr int BM = 128, BN = 256, BK = 32, S = 4;
constexpr int NSTAGE = KDIM / BK;            // 32
constexpr int A_LDH = 40;
constexpr int B_LDH = 264;
constexpr int A_BYTES = BM * A_LDH * 2;      // 10240
constexpr int B_BYTES = BK * B_LDH * 2;      // 16896
constexpr int B_BASE = S * A_BYTES;          // 40960
constexpr int SMEM_SZ = B_BASE + S * B_BYTES; // 108544 B

__global__ __launch_bounds__(256, 1) void gemm_mma(const __half* __restrict__ xh,
                                                   const __half* __restrict__ sh) {
    extern __shared__ __align__(1024) char smem[];
    const uint32_t sb = smem_u32(smem);
    const uint32_t sbB = sb + B_BASE;

    const int tid  = threadIdx.x;
    const int lane = tid & 31;
    const int wid  = tid >> 5;
    const int wm   = wid >> 2;   // 0..1
    const int wn   = wid & 3;    // 0..3

    const __half* A; const __half* B; __half* C; int ldn, m0, n0;
    int bid = blockIdx.x;
    if (bid < 768) {
        A = xh; B = g_Uh; C = g_Ux; ldn = 3072;
        m0 = (bid & 63) * BM; n0 = (bid >> 6) * BN;
    } else {
        int t = bid - 768, g = t >> 8, tt = t & 255;
        A = sh; B = g ? g_Wgh : g_Wrh; C = g ? g_SG : g_SR; ldn = 1024;
        m0 = (tt & 63) * BM; n0 = (tt >> 6) * BN;
    }

    auto load_stage = [&](int st) {
        const int buf = st & (S - 1);
        const __half* Ag = A + (size_t)m0 * KDIM + st * BK;
        const uint32_t ab = sb + (uint32_t)(buf * A_BYTES);
#pragma unroll
        for (int i = 0; i < 2; i++) {
            int idx = tid + i * 256;
            int r = idx >> 2, c = idx & 3;
            cp16(ab + (uint32_t)(r * (A_LDH * 2) + c * 16),
                 Ag + (size_t)r * KDIM + c * 8);
        }
        const __half* Bg = B + (size_t)st * BK * ldn + n0;
        const uint32_t bb = sbB + (uint32_t)(buf * B_BYTES);
#pragma unroll
        for (int i = 0; i < 4; i++) {
            int idx = tid + i * 256;
            int k = idx >> 5, c = idx & 31;
            cp16(bb + (uint32_t)(k * (B_LDH * 2) + c * 16),
                 Bg + (size_t)k * ldn + c * 8);
        }
        CP_COMMIT();
    };

    load_stage(0);
    load_stage(1);
    load_stage(2);

    float acc[4][8][4];
#pragma unroll
    for (int mt = 0; mt < 4; mt++)
#pragma unroll
        for (int nt = 0; nt < 8; nt++)
#pragma unroll
            for (int j = 0; j < 4; j++) acc[mt][nt][j] = 0.0f;

    const int lr = lane & 15;
    const int lc = lane >> 4;

    for (int ks = 0; ks < NSTAGE; ks++) {
        CP_WAIT(2);
        __syncthreads();
        if (ks + 3 < NSTAGE) load_stage(ks + 3); else CP_COMMIT();

        const int buf = ks & (S - 1);
        const uint32_t abase = sb + (uint32_t)buf * A_BYTES +
                               (uint32_t)((wm * 64 + lr) * (A_LDH * 2) + lc * 16);
        const uint32_t bbase = sbB + (uint32_t)buf * B_BYTES +
                               (uint32_t)(lr * (B_LDH * 2) + (wn * 64 + lc * 8) * 2);

#pragma unroll
        for (int kk = 0; kk < BK; kk += 16) {
            uint32_t af[4][4];
#pragma unroll
            for (int mt = 0; mt < 4; mt++)
                ldsm_x4(af[mt], abase + mt * 16 * (A_LDH * 2) + kk * 2);
            uint32_t bf[4][4];
#pragma unroll
            for (int nc = 0; nc < 4; nc++)
                ldsm_x4_t(bf[nc], bbase + kk * (B_LDH * 2) + nc * 32);
#pragma unroll
            for (int mt = 0; mt < 4; mt++)
#pragma unroll
                for (int nc = 0; nc < 4; nc++) {
                    mma_f16(acc[mt][2 * nc],     af[mt], bf[nc]);
                    mma_f16(acc[mt][2 * nc + 1], af[mt], bf[nc] + 2);
                }
        }
        __syncthreads();
    }

    // ---- epilogue: fp16 half2 stores ----
    const int crow = m0 + wm * 64 + (lane >> 2);
    const int ccol = n0 + wn * 64 + (lane & 3) * 2;
#pragma unroll
    for (int mt = 0; mt < 4; mt++)
#pragma unroll
        for (int nt = 0; nt < 8; nt++) {
            __half* p0 = C + (size_t)(crow + mt * 16) * ldn + ccol + nt * 8;
            *reinterpret_cast<__half2*>(p0) =
                __floats2half2_rn(acc[mt][nt][0], acc[mt][nt][1]);
            *reinterpret_cast<__half2*>(p0 + 8 * ldn) =
                __floats2half2_rn(acc[mt][nt][2], acc[mt][nt][3]);
        }
}

// ---------------- fused butterfly + gates: 1 warp per row, no smem ---------
// layout: j = e*64 + lane*2 + p ; e in [0,16), p in {0,1}; v[e*2+p] = h[j]
// stages i=0..3  (hb=9..6): in-register across e-bit (hb-6)
// stages i=4..8  (hb=5..1): shfl_xor across lane-bit (hb-1)
// stage  i=9     (hb=0)   : in-register p-pair
__global__ __launch_bounds__(256) void fuse_kernel(
    const float* __restrict__ state,
    const float* __restrict__ br, const float* __restrict__ bg,
    const float* __restrict__ bc, float* __restrict__ out)
{
    const int lane = threadIdx.x & 31;
    const int w    = threadIdx.x >> 5;
    const int row  = blockIdx.x * 8 + w;
    const float* st = state + (size_t)row * DOUT;

    float v[32];
#pragma unroll
    for (int e = 0; e < 16; e++) {
        float2 t = *reinterpret_cast<const float2*>(st + e * 64 + lane * 2);
        v[e * 2] = t.x; v[e * 2 + 1] = t.y;
    }

    // stages i = 0..3 (e-bit)
#pragma unroll
    for (int i = 0; i < 4; i++) {
        const int hb = 9 - i;
        const int eb = 1 << (hb - 6);
#pragma unroll
        for (int e = 0; e < 16; e++) {
            if (e & eb) continue;
#pragma unroll
            for (int p = 0; p < 2; p++) {
                int m = e * 64 + lane * 2 + p;
                int a = ((m & ((1 << hb) - 1)) << i) | (m >> (hb + 1));
                float2 cs = g_cs[i * 512 + a];
                float h0 = v[e * 2 + p], h1 = v[(e ^ eb) * 2 + p];
                v[e * 2 + p]        = cs.x * h0 - cs.y * h1;
                v[(e ^ eb) * 2 + p] = cs.y * h0 + cs.x * h1;
            }
        }
    }

    // stages i = 4..8 (lane-bit)
#pragma unroll
    for (int i = 4; i < 9; i++) {
        const int hb = 9 - i;
        const int lm = 1 << (hb - 1);
        const bool up = (lane & lm) != 0;
#pragma unroll
        for (int k = 0; k < 32; k++) {
            int e = k >> 1, p = k & 1;
            float other = __shfl_xor_sync(0xffffffffu, v[k], lm);
            int m = (e * 64 + lane * 2 + p) & ~(1 << hb);
            int a = ((m & ((1 << hb) - 1)) << i) | (m >> (hb + 1));
            float2 cs = g_cs[i * 512 + a];
            v[k] = up ? (cs.y * other + cs.x * v[k]) : (cs.x * v[k] - cs.y * other);
        }
    }

    // stage i = 9 (p-pair)
#pragma unroll
    for (int e = 0; e < 16; e++) {
        float2 cs = g_cs[9 * 512 + e * 32 + lane];
        float h0 = v[e * 2], h1 = v[e * 2 + 1];
        v[e * 2]     = cs.x * h0 - cs.y * h1;
        v[e * 2 + 1] = cs.y * h0 + cs.x * h1;
    }

    // gates + modReLU + output
    const __half* uxr = g_Ux + (size_t)row * 3072;
    const __half* srr = g_SR + (size_t)row * DOUT;
    const __half* sgr = g_SG + (size_t)row * DOUT;
    float* outr = out + (size_t)row * DOUT;

#pragma unroll
    for (int e = 0; e < 16; e++) {
        int j = e * 64 + lane * 2;
        float2 ucx = __half22float2(*reinterpret_cast<const __half2*>(uxr + j));
        float2 urx = __half22float2(*reinterpret_cast<const __half2*>(uxr + 1024 + j));
        float2 ugx = __half22float2(*reinterpret_cast<const __half2*>(uxr + 2048 + j));
        float2 srv = __half22float2(*reinterpret_cast<const __half2*>(srr + j));
        float2 sgv = __half22float2(*reinterpret_cast<const __half2*>(sgr + j));
        float2 stv = *reinterpret_cast<const float2*>(st + j);
        float2 brv = *reinterpret_cast<const float2*>(br + j);
        float2 bgv = *reinterpret_cast<const float2*>(bg + j);
        float2 bcv = *reinterpret_cast<const float2*>(bc + j);

        float2 o;
        {
            float rv = 1.0f / (1.0f + expf(-(urx.x + srv.x + brv.x)));
            float gv = 1.0f / (1.0f + expf(-(ugx.x + sgv.x + bgv.x)));
            float pre = rv * v[e * 2] + ucx.x;
            float mag = fabsf(pre) + 0.001f + bcv.x;
            float sgn = (pre > 0.0f) ? 1.0f : ((pre < 0.0f) ? -1.0f : 0.0f);
            o.x = gv * stv.x + (1.0f - gv) * (sgn * fmaxf(mag, 0.0f));
        }
        {
            float rv = 1.0f / (1.0f + expf(-(urx.y + srv.y + brv.y)));
            float gv = 1.0f / (1.0f + expf(-(ugx.y + sgv.y + bgv.y)));
            float pre = rv * v[e * 2 + 1] + ucx.y;
            float mag = fabsf(pre) + 0.001f + bcv.y;
            float sgn = (pre > 0.0f) ? 1.0f : ((pre < 0.0f) ? -1.0f : 0.0f);
            o.y = gv * stv.y + (1.0f - gv) * (sgn * fmaxf(mag, 0.0f));
        }
        *reinterpret_cast<float2*>(outr + j) = o;
    }
}

// ---------------- launch ---------------------------------------------------
extern "C" void kernel_launch(void* const* d_in, const int* in_sizes, int n_in,
                              void* d_out, int out_size)
{
    const float* x     = (const float*)d_in[0];
    const float* state = (const float*)d_in[1];
    const float* theta = (const float*)d_in[2];
    const float* U     = (const float*)d_in[3];
    const float* W_r   = (const float*)d_in[4];
    const float* W_g   = (const float*)d_in[5];
    const float* br    = (const float*)d_in[6];
    const float* bg    = (const float*)d_in[7];
    const float* bc    = (const float*)d_in[8];
    float* out = (float*)d_out;

    __half *xh, *sh;
    cudaGetSymbolAddress((void**)&xh, g_xh);
    cudaGetSymbolAddress((void**)&sh, g_sh);

    static bool attr_done = false;
    if (!attr_done) {
        cudaFuncSetAttribute(gemm_mma, cudaFuncAttributeMaxDynamicSharedMemorySize, SMEM_SZ);
        attr_done = true;
    }

    trig_kernel<<<NCAP, 512>>>(theta);
    f2h_all<<<dim3(384, 5), 256>>>(x, state, U, W_r, W_g);
    gemm_mma<<<1280, 256, SMEM_SZ>>>(xh, sh);
    fuse_kernel<<<NROWS / 8, 256>>>(state, br, bg, bc, out);
}

// round 12
// speedup vs baseline: 1.1495x; 1.1495x over previous
#include <cuda_runtime.h>
#include <cuda_fp16.h>
#include <cstdint>

#define DOUT 1024
#define NROWS 8192
#define NCAP 10
#define KDIM 1024

// ---------------- scratch (device globals: allocation-rule-safe) ----------
__device__ float2 g_tab[NCAP * 1024];   // [stage][k=0..31][lane=0..31] consumption-order
__device__ __half g_Ux[(size_t)NROWS * 3072];
__device__ __half g_SR[(size_t)NROWS * 1024];
__device__ __half g_SG[(size_t)NROWS * 1024];
__device__ __half g_xh[(size_t)NROWS * 1024];
__device__ __half g_sh[(size_t)NROWS * 1024];
__device__ __half g_Uh[(size_t)1024 * 3072];
__device__ __half g_Wrh[(size_t)1024 * 1024];
__device__ __half g_Wgh[(size_t)1024 * 1024];

// ---------------- helpers ---------------------------------------------------
__device__ __forceinline__ uint32_t smem_u32(const void* p) {
    uint32_t a;
    asm("{ .reg .u64 t; cvta.to.shared.u64 t, %1; cvt.u32.u64 %0, t; }" : "=r"(a) : "l"(p));
    return a;
}
__device__ __forceinline__ void cp16(uint32_t s, const void* g) {
    asm volatile("cp.async.cg.shared.global [%0], [%1], 16;" :: "r"(s), "l"(g));
}
#define CP_COMMIT() asm volatile("cp.async.commit_group;" ::: "memory")
#define CP_WAIT(n)  asm volatile("cp.async.wait_group %0;" :: "n"(n) : "memory")

__device__ __forceinline__ void ldsm_x4(uint32_t* r, uint32_t addr) {
    asm volatile("ldmatrix.sync.aligned.m8n8.x4.shared.b16 {%0,%1,%2,%3}, [%4];"
                 : "=r"(r[0]), "=r"(r[1]), "=r"(r[2]), "=r"(r[3]) : "r"(addr));
}
__device__ __forceinline__ void ldsm_x4_t(uint32_t* r, uint32_t addr) {
    asm volatile("ldmatrix.sync.aligned.m8n8.x4.trans.shared.b16 {%0,%1,%2,%3}, [%4];"
                 : "=r"(r[0]), "=r"(r[1]), "=r"(r[2]), "=r"(r[3]) : "r"(addr));
}
__device__ __forceinline__ void mma_f16(float* d, const uint32_t* a, const uint32_t* b) {
    asm volatile(
        "mma.sync.aligned.m16n8k16.row.col.f32.f16.f16.f32 "
        "{%0,%1,%2,%3}, {%4,%5,%6,%7}, {%8,%9}, {%0,%1,%2,%3};"
        : "+f"(d[0]), "+f"(d[1]), "+f"(d[2]), "+f"(d[3])
        : "r"(a[0]), "r"(a[1]), "r"(a[2]), "r"(a[3]), "r"(b[0]), "r"(b[1]));
}

// ---------------- permuted trig table (consumption order) -------------------
// Element m = e*64 + lane*2 + p (k = e*2+p). For stage i (hb = 9-i):
//   m_low = m & ~(1<<hb);  a = ((m_low & ((1<<hb)-1)) << i) | (m_low >> (hb+1))
// g_tab[i*1024 + k*32 + lane] = (cos theta[i][a], sin theta[i][a])
__global__ void perm_kernel(const float* __restrict__ theta) {
    int i = blockIdx.x;
    int tid = threadIdx.x;            // = k*32 + lane
    int k = tid >> 5, lane = tid & 31;
    int e = k >> 1, p = k & 1;
    int hb = 9 - i;
    int m = e * 64 + lane * 2 + p;
    int m_low = m & ~(1 << hb);
    int a = ((m_low & ((1 << hb) - 1)) << i) | (m_low >> (hb + 1));
    float s, c;
    sincosf(theta[i * 512 + a], &s, &c);
    g_tab[i * 1024 + tid] = make_float2(c, s);
}

// ---------------- fp32 -> fp16 convert (x, state, U, Wr, Wg) ---------------
__global__ __launch_bounds__(256) void f2h_all(const float* __restrict__ x,
                                               const float* __restrict__ state,
                                               const float* __restrict__ U,
                                               const float* __restrict__ Wr,
                                               const float* __restrict__ Wg) {
    const float* in; __half* out; int n4;
    switch (blockIdx.y) {
        case 0: in = x;     out = g_xh;  n4 = NROWS * 1024 / 4; break;
        case 1: in = state; out = g_sh;  n4 = NROWS * 1024 / 4; break;
        case 2: in = U;     out = g_Uh;  n4 = 1024 * 3072 / 4;  break;
        case 3: in = Wr;    out = g_Wrh; n4 = 1024 * 1024 / 4;  break;
        default: in = Wg;   out = g_Wgh; n4 = 1024 * 1024 / 4;  break;
    }
    int i = blockIdx.x * 256 + threadIdx.x;
    int stride = gridDim.x * 256;
    for (; i < n4; i += stride) {
        float4 v = reinterpret_cast<const float4*>(in)[i];
        __half2 h0 = __floats2half2_rn(v.x, v.y);
        __half2 h1 = __floats2half2_rn(v.z, v.w);
        uint2 u;
        u.x = *reinterpret_cast<const uint32_t*>(&h0);
        u.y = *reinterpret_cast<const uint32_t*>(&h1);
        reinterpret_cast<uint2*>(out)[i] = u;
    }
}

// ---------------- mma.sync fp16 GEMM (fp16 output) --------------------------
constexpr int BM = 128, BN = 256, BK = 32, S = 4;
constexpr int NSTAGE = KDIM / BK;            // 32
constexpr int A_LDH = 40;
constexpr int B_LDH = 264;
constexpr int A_BYTES = BM * A_LDH * 2;      // 10240
constexpr int B_BYTES = BK * B_LDH * 2;      // 16896
constexpr int B_BASE = S * A_BYTES;          // 40960
constexpr int SMEM_SZ = B_BASE + S * B_BYTES; // 108544 B

__global__ __launch_bounds__(256, 1) void gemm_mma(const __half* __restrict__ xh,
                                                   const __half* __restrict__ sh) {
    extern __shared__ __align__(1024) char smem[];
    const uint32_t sb = smem_u32(smem);
    const uint32_t sbB = sb + B_BASE;

    const int tid  = threadIdx.x;
    const int lane = tid & 31;
    const int wid  = tid >> 5;
    const int wm   = wid >> 2;   // 0..1
    const int wn   = wid & 3;    // 0..3

    const __half* A; const __half* B; __half* C; int ldn, m0, n0;
    int bid = blockIdx.x;
    if (bid < 768) {
        A = xh; B = g_Uh; C = g_Ux; ldn = 3072;
        m0 = (bid & 63) * BM; n0 = (bid >> 6) * BN;
    } else {
        int t = bid - 768, g = t >> 8, tt = t & 255;
        A = sh; B = g ? g_Wgh : g_Wrh; C = g ? g_SG : g_SR; ldn = 1024;
        m0 = (tt & 63) * BM; n0 = (tt >> 6) * BN;
    }

    auto load_stage = [&](int st) {
        const int buf = st & (S - 1);
        const __half* Ag = A + (size_t)m0 * KDIM + st * BK;
        const uint32_t ab = sb + (uint32_t)(buf * A_BYTES);
#pragma unroll
        for (int i = 0; i < 2; i++) {
            int idx = tid + i * 256;
            int r = idx >> 2, c = idx & 3;
            cp16(ab + (uint32_t)(r * (A_LDH * 2) + c * 16),
                 Ag + (size_t)r * KDIM + c * 8);
        }
        const __half* Bg = B + (size_t)st * BK * ldn + n0;
        const uint32_t bb = sbB + (uint32_t)(buf * B_BYTES);
#pragma unroll
        for (int i = 0; i < 4; i++) {
            int idx = tid + i * 256;
            int k = idx >> 5, c = idx & 31;
            cp16(bb + (uint32_t)(k * (B_LDH * 2) + c * 16),
                 Bg + (size_t)k * ldn + c * 8);
        }
        CP_COMMIT();
    };

    load_stage(0);
    load_stage(1);
    load_stage(2);

    float acc[4][8][4];
#pragma unroll
    for (int mt = 0; mt < 4; mt++)
#pragma unroll
        for (int nt = 0; nt < 8; nt++)
#pragma unroll
            for (int j = 0; j < 4; j++) acc[mt][nt][j] = 0.0f;

    const int lr = lane & 15;
    const int lc = lane >> 4;

    for (int ks = 0; ks < NSTAGE; ks++) {
        CP_WAIT(2);
        __syncthreads();
        if (ks + 3 < NSTAGE) load_stage(ks + 3); else CP_COMMIT();

        const int buf = ks & (S - 1);
        const uint32_t abase = sb + (uint32_t)buf * A_BYTES +
                               (uint32_t)((wm * 64 + lr) * (A_LDH * 2) + lc * 16);
        const uint32_t bbase = sbB + (uint32_t)buf * B_BYTES +
                               (uint32_t)(lr * (B_LDH * 2) + (wn * 64 + lc * 8) * 2);

#pragma unroll
        for (int kk = 0; kk < BK; kk += 16) {
            uint32_t af[4][4];
#pragma unroll
            for (int mt = 0; mt < 4; mt++)
                ldsm_x4(af[mt], abase + mt * 16 * (A_LDH * 2) + kk * 2);
            uint32_t bf[4][4];
#pragma unroll
            for (int nc = 0; nc < 4; nc++)
                ldsm_x4_t(bf[nc], bbase + kk * (B_LDH * 2) + nc * 32);
#pragma unroll
            for (int mt = 0; mt < 4; mt++)
#pragma unroll
                for (int nc = 0; nc < 4; nc++) {
                    mma_f16(acc[mt][2 * nc],     af[mt], bf[nc]);
                    mma_f16(acc[mt][2 * nc + 1], af[mt], bf[nc] + 2);
                }
        }
        __syncthreads();
    }

    // ---- epilogue: fp16 half2 stores ----
    const int crow = m0 + wm * 64 + (lane >> 2);
    const int ccol = n0 + wn * 64 + (lane & 3) * 2;
#pragma unroll
    for (int mt = 0; mt < 4; mt++)
#pragma unroll
        for (int nt = 0; nt < 8; nt++) {
            __half* p0 = C + (size_t)(crow + mt * 16) * ldn + ccol + nt * 8;
            *reinterpret_cast<__half2*>(p0) =
                __floats2half2_rn(acc[mt][nt][0], acc[mt][nt][1]);
            *reinterpret_cast<__half2*>(p0 + 8 * ldn) =
                __floats2half2_rn(acc[mt][nt][2], acc[mt][nt][3]);
        }
}

// ---------------- fused butterfly + gates: 1 warp per row, coalesced table --
// layout: j = e*64 + lane*2 + p ; v[e*2+p] = h[j]; k = e*2+p
// stages i=0..3 : in-register across e-bit;  i=4..8 : shfl_xor;  i=9 : p-pair
// all table reads: g_tab[i*1024 + k*32 + lane]  (contiguous across lanes)
__global__ __launch_bounds__(256) void fuse_kernel(
    const float* __restrict__ state,
    const float* __restrict__ br, const float* __restrict__ bg,
    const float* __restrict__ bc, float* __restrict__ out)
{
    const int lane = threadIdx.x & 31;
    const int w    = threadIdx.x >> 5;
    const int row  = blockIdx.x * 8 + w;
    const float* st = state + (size_t)row * DOUT;

    float v[32];
#pragma unroll
    for (int e = 0; e < 16; e++) {
        float2 t = *reinterpret_cast<const float2*>(st + e * 64 + lane * 2);
        v[e * 2] = t.x; v[e * 2 + 1] = t.y;
    }

    // stages i = 0..3 (e-bit)
#pragma unroll
    for (int i = 0; i < 4; i++) {
        const int hb = 9 - i;
        const int eb = 1 << (hb - 6);
        const float2* tab = g_tab + i * 1024;
#pragma unroll
        for (int e = 0; e < 16; e++) {
            if (e & eb) continue;
#pragma unroll
            for (int p = 0; p < 2; p++) {
                float2 cs = tab[(e * 2 + p) * 32 + lane];
                float h0 = v[e * 2 + p], h1 = v[(e ^ eb) * 2 + p];
                v[e * 2 + p]        = cs.x * h0 - cs.y * h1;
                v[(e ^ eb) * 2 + p] = cs.y * h0 + cs.x * h1;
            }
        }
    }

    // stages i = 4..8 (lane-bit)
#pragma unroll
    for (int i = 4; i < 9; i++) {
        const int lm = 1 << (9 - i - 1);
        const bool up = (lane & lm) != 0;
        const float2* tab = g_tab + i * 1024;
#pragma unroll
        for (int k = 0; k < 32; k++) {
            float other = __shfl_xor_sync(0xffffffffu, v[k], lm);
            float2 cs = tab[k * 32 + lane];
            v[k] = up ? (cs.y * other + cs.x * v[k]) : (cs.x * v[k] - cs.y * other);
        }
    }

    // stage i = 9 (p-pair)
    {
        const float2* tab = g_tab + 9 * 1024;
#pragma unroll
        for (int e = 0; e < 16; e++) {
            float2 cs = tab[(e * 2) * 32 + lane];
            float h0 = v[e * 2], h1 = v[e * 2 + 1];
            v[e * 2]     = cs.x * h0 - cs.y * h1;
            v[e * 2 + 1] = cs.y * h0 + cs.x * h1;
        }
    }

    // gates + modReLU + output
    const __half* uxr = g_Ux + (size_t)row * 3072;
    const __half* srr = g_SR + (size_t)row * DOUT;
    const __half* sgr = g_SG + (size_t)row * DOUT;
    float* outr = out + (size_t)row * DOUT;

#pragma unroll
    for (int e = 0; e < 16; e++) {
        int j = e * 64 + lane * 2;
        float2 ucx = __half22float2(*reinterpret_cast<const __half2*>(uxr + j));
        float2 urx = __half22float2(*reinterpret_cast<const __half2*>(uxr + 1024 + j));
        float2 ugx = __half22float2(*reinterpret_cast<const __half2*>(uxr + 2048 + j));
        float2 srv = __half22float2(*reinterpret_cast<const __half2*>(srr + j));
        float2 sgv = __half22float2(*reinterpret_cast<const __half2*>(sgr + j));
        float2 stv = *reinterpret_cast<const float2*>(st + j);
        float2 brv = *reinterpret_cast<const float2*>(br + j);
        float2 bgv = *reinterpret_cast<const float2*>(bg + j);
        float2 bcv = *reinterpret_cast<const float2*>(bc + j);

        float2 o;
        {
            float rv = 1.0f / (1.0f + expf(-(urx.x + srv.x + brv.x)));
            float gv = 1.0f / (1.0f + expf(-(ugx.x + sgv.x + bgv.x)));
            float pre = rv * v[e * 2] + ucx.x;
            float mag = fabsf(pre) + 0.001f + bcv.x;
            float sgn = (pre > 0.0f) ? 1.0f : ((pre < 0.0f) ? -1.0f : 0.0f);
            o.x = gv * stv.x + (1.0f - gv) * (sgn * fmaxf(mag, 0.0f));
        }
        {
            float rv = 1.0f / (1.0f + expf(-(urx.y + srv.y + brv.y)));
            float gv = 1.0f / (1.0f + expf(-(ugx.y + sgv.y + bgv.y)));
            float pre = rv * v[e * 2 + 1] + ucx.y;
            float mag = fabsf(pre) + 0.001f + bcv.y;
            float sgn = (pre > 0.0f) ? 1.0f : ((pre < 0.0f) ? -1.0f : 0.0f);
            o.y = gv * stv.y + (1.0f - gv) * (sgn * fmaxf(mag, 0.0f));
        }
        *reinterpret_cast<float2*>(outr + j) = o;
    }
}

// ---------------- launch ---------------------------------------------------
extern "C" void kernel_launch(void* const* d_in, const int* in_sizes, int n_in,
                              void* d_out, int out_size)
{
    const float* x     = (const float*)d_in[0];
    const float* state = (const float*)d_in[1];
    const float* theta = (const float*)d_in[2];
    const float* U     = (const float*)d_in[3];
    const float* W_r   = (const float*)d_in[4];
    const float* W_g   = (const float*)d_in[5];
    const float* br    = (const float*)d_in[6];
    const float* bg    = (const float*)d_in[7];
    const float* bc    = (const float*)d_in[8];
    float* out = (float*)d_out;

    __half *xh, *sh;
    cudaGetSymbolAddress((void**)&xh, g_xh);
    cudaGetSymbolAddress((void**)&sh, g_sh);

    static bool attr_done = false;
    if (!attr_done) {
        cudaFuncSetAttribute(gemm_mma, cudaFuncAttributeMaxDynamicSharedMemorySize, SMEM_SZ);
        attr_done = true;
    }

    perm_kernel<<<NCAP, 1024>>>(theta);
    f2h_all<<<dim3(384, 5), 256>>>(x, state, U, W_r, W_g);
    gemm_mma<<<1280, 256, SMEM_SZ>>>(xh, sh);
    fuse_kernel<<<NROWS / 8, 256>>>(state, br, bg, bc, out);
}

// round 14
// speedup vs baseline: 1.1671x; 1.0153x over previous
#include <cuda_runtime.h>
#include <cuda_fp16.h>
#include <cstdint>

#define DOUT 1024
#define NROWS 8192
#define NCAP 10
#define KDIM 1024

// ---------------- scratch (device globals: allocation-rule-safe) ----------
__device__ float2 g_tab[NCAP * 1024];   // [stage][k=0..31][lane=0..31] consumption-order
__device__ __half g_Ux[(size_t)NROWS * 3072];
__device__ __half g_SR[(size_t)NROWS * 1024];
__device__ __half g_SG[(size_t)NROWS * 1024];
__device__ __half g_xh[(size_t)NROWS * 1024];
__device__ __half g_sh[(size_t)NROWS * 1024];
__device__ __half g_Uh[(size_t)1024 * 3072];
__device__ __half g_Wrh[(size_t)1024 * 1024];
__device__ __half g_Wgh[(size_t)1024 * 1024];

// ---------------- helpers ---------------------------------------------------
__device__ __forceinline__ uint32_t smem_u32(const void* p) {
    uint32_t a;
    asm("{ .reg .u64 t; cvta.to.shared.u64 t, %1; cvt.u32.u64 %0, t; }" : "=r"(a) : "l"(p));
    return a;
}
__device__ __forceinline__ void cp16(uint32_t s, const void* g) {
    asm volatile("cp.async.cg.shared.global [%0], [%1], 16;" :: "r"(s), "l"(g));
}
#define CP_COMMIT() asm volatile("cp.async.commit_group;" ::: "memory")
#define CP_WAIT(n)  asm volatile("cp.async.wait_group %0;" :: "n"(n) : "memory")

__device__ __forceinline__ void ldsm_x4(uint32_t* r, uint32_t addr) {
    asm volatile("ldmatrix.sync.aligned.m8n8.x4.shared.b16 {%0,%1,%2,%3}, [%4];"
                 : "=r"(r[0]), "=r"(r[1]), "=r"(r[2]), "=r"(r[3]) : "r"(addr));
}
__device__ __forceinline__ void ldsm_x4_t(uint32_t* r, uint32_t addr) {
    asm volatile("ldmatrix.sync.aligned.m8n8.x4.trans.shared.b16 {%0,%1,%2,%3}, [%4];"
                 : "=r"(r[0]), "=r"(r[1]), "=r"(r[2]), "=r"(r[3]) : "r"(addr));
}
__device__ __forceinline__ void mma_f16(float* d, const uint32_t* a, const uint32_t* b) {
    asm volatile(
        "mma.sync.aligned.m16n8k16.row.col.f32.f16.f16.f32 "
        "{%0,%1,%2,%3}, {%4,%5,%6,%7}, {%8,%9}, {%0,%1,%2,%3};"
        : "+f"(d[0]), "+f"(d[1]), "+f"(d[2]), "+f"(d[3])
        : "r"(a[0]), "r"(a[1]), "r"(a[2]), "r"(a[3]), "r"(b[0]), "r"(b[1]));
}

// ---------------- permuted trig table (consumption order) -------------------
__global__ void perm_kernel(const float* __restrict__ theta) {
    int i = blockIdx.x;
    int tid = threadIdx.x;            // = k*32 + lane
    int k = tid >> 5, lane = tid & 31;
    int e = k >> 1, p = k & 1;
    int hb = 9 - i;
    int m = e * 64 + lane * 2 + p;
    int m_low = m & ~(1 << hb);
    int a = ((m_low & ((1 << hb) - 1)) << i) | (m_low >> (hb + 1));
    float s, c;
    sincosf(theta[i * 512 + a], &s, &c);
    g_tab[i * 1024 + tid] = make_float2(c, s);
}

// ---------------- fp32 -> fp16 convert (x, state, U, Wr, Wg) ---------------
__global__ __launch_bounds__(256) void f2h_all(const float* __restrict__ x,
                                               const float* __restrict__ state,
                                               const float* __restrict__ U,
                                               const float* __restrict__ Wr,
                                               const float* __restrict__ Wg) {
    const float* in; __half* out; int n4;
    switch (blockIdx.y) {
        case 0: in = x;     out = g_xh;  n4 = NROWS * 1024 / 4; break;
        case 1: in = state; out = g_sh;  n4 = NROWS * 1024 / 4; break;
        case 2: in = U;     out = g_Uh;  n4 = 1024 * 3072 / 4;  break;
        case 3: in = Wr;    out = g_Wrh; n4 = 1024 * 1024 / 4;  break;
        default: in = Wg;   out = g_Wgh; n4 = 1024 * 1024 / 4;  break;
    }
    int i = blockIdx.x * 256 + threadIdx.x;
    int stride = gridDim.x * 256;
    for (; i < n4; i += stride) {
        float4 v = reinterpret_cast<const float4*>(in)[i];
        __half2 h0 = __floats2half2_rn(v.x, v.y);
        __half2 h1 = __floats2half2_rn(v.z, v.w);
        uint2 u;
        u.x = *reinterpret_cast<const uint32_t*>(&h0);
        u.y = *reinterpret_cast<const uint32_t*>(&h1);
        reinterpret_cast<uint2*>(out)[i] = u;
    }
}

// ---------------- mma.sync fp16 GEMM (fp16 output) --------------------------
constexpr int BM = 128, BN = 256, BK = 32, S = 4;
constexpr int NSTAGE = KDIM / BK;            // 32
constexpr int A_LDH = 40;
constexpr int B_LDH = 264;
constexpr int A_BYTES = BM * A_LDH * 2;      // 10240
constexpr int B_BYTES = BK * B_LDH * 2;      // 16896
constexpr int B_BASE = S * A_BYTES;          // 40960
constexpr int SMEM_SZ = B_BASE + S * B_BYTES; // 108544 B

__global__ __launch_bounds__(256, 1) void gemm_mma(const __half* __restrict__ xh,
                                                   const __half* __restrict__ sh) {
    extern __shared__ __align__(1024) char smem[];
    const uint32_t sb = smem_u32(smem);
    const uint32_t sbB = sb + B_BASE;

    const int tid  = threadIdx.x;
    const int lane = tid & 31;
    const int wid  = tid >> 5;
    const int wm   = wid >> 2;   // 0..1
    const int wn   = wid & 3;    // 0..3

    const __half* A; const __half* B; __half* C; int ldn, m0, n0;
    int bid = blockIdx.x;
    if (bid < 768) {
        A = xh; B = g_Uh; C = g_Ux; ldn = 3072;
        m0 = (bid & 63) * BM; n0 = (bid >> 6) * BN;
    } else {
        int t = bid - 768, g = t >> 8, tt = t & 255;
        A = sh; B = g ? g_Wgh : g_Wrh; C = g ? g_SG : g_SR; ldn = 1024;
        m0 = (tt & 63) * BM; n0 = (tt >> 6) * BN;
    }

    auto load_stage = [&](int st) {
        const int buf = st & (S - 1);
        const __half* Ag = A + (size_t)m0 * KDIM + st * BK;
        const uint32_t ab = sb + (uint32_t)(buf * A_BYTES);
#pragma unroll
        for (int i = 0; i < 2; i++) {
            int idx = tid + i * 256;
            int r = idx >> 2, c = idx & 3;
            cp16(ab + (uint32_t)(r * (A_LDH * 2) + c * 16),
                 Ag + (size_t)r * KDIM + c * 8);
        }
        const __half* Bg = B + (size_t)st * BK * ldn + n0;
        const uint32_t bb = sbB + (uint32_t)(buf * B_BYTES);
#pragma unroll
        for (int i = 0; i < 4; i++) {
            int idx = tid + i * 256;
            int k = idx >> 5, c = idx & 31;
            cp16(bb + (uint32_t)(k * (B_LDH * 2) + c * 16),
                 Bg + (size_t)k * ldn + c * 8);
        }
        CP_COMMIT();
    };

    load_stage(0);
    load_stage(1);
    load_stage(2);

    float acc[4][8][4];
#pragma unroll
    for (int mt = 0; mt < 4; mt++)
#pragma unroll
        for (int nt = 0; nt < 8; nt++)
#pragma unroll
            for (int j = 0; j < 4; j++) acc[mt][nt][j] = 0.0f;

    const int lr = lane & 15;
    const int lc = lane >> 4;

    for (int ks = 0; ks < NSTAGE; ks++) {
        CP_WAIT(2);
        __syncthreads();
        if (ks + 3 < NSTAGE) load_stage(ks + 3); else CP_COMMIT();

        const int buf = ks & (S - 1);
        const uint32_t abase = sb + (uint32_t)buf * A_BYTES +
                               (uint32_t)((wm * 64 + lr) * (A_LDH * 2) + lc * 16);
        const uint32_t bbase = sbB + (uint32_t)buf * B_BYTES +
                               (uint32_t)(lr * (B_LDH * 2) + (wn * 64 + lc * 8) * 2);

#pragma unroll
        for (int kk = 0; kk < BK; kk += 16) {
            uint32_t af[4][4];
#pragma unroll
            for (int mt = 0; mt < 4; mt++)
                ldsm_x4(af[mt], abase + mt * 16 * (A_LDH * 2) + kk * 2);
            uint32_t bf[4][4];
#pragma unroll
            for (int nc = 0; nc < 4; nc++)
                ldsm_x4_t(bf[nc], bbase + kk * (B_LDH * 2) + nc * 32);
#pragma unroll
            for (int mt = 0; mt < 4; mt++)
#pragma unroll
                for (int nc = 0; nc < 4; nc++) {
                    mma_f16(acc[mt][2 * nc],     af[mt], bf[nc]);
                    mma_f16(acc[mt][2 * nc + 1], af[mt], bf[nc] + 2);
                }
        }
        __syncthreads();
    }

    // ---- epilogue: fp16 half2 stores ----
    const int crow = m0 + wm * 64 + (lane >> 2);
    const int ccol = n0 + wn * 64 + (lane & 3) * 2;
#pragma unroll
    for (int mt = 0; mt < 4; mt++)
#pragma unroll
        for (int nt = 0; nt < 8; nt++) {
            __half* p0 = C + (size_t)(crow + mt * 16) * ldn + ccol + nt * 8;
            *reinterpret_cast<__half2*>(p0) =
                __floats2half2_rn(acc[mt][nt][0], acc[mt][nt][1]);
            *reinterpret_cast<__half2*>(p0 + 8 * ldn) =
                __floats2half2_rn(acc[mt][nt][2], acc[mt][nt][3]);
        }
}

// ---------------- fused butterfly + gates: smem table, 32 rows/CTA ----------
// layout: j = e*64 + lane*2 + p ; v[e*2+p] = h[j]; k = e*2+p
// stages i=0..3 : in-register across e-bit;  i=4..8 : shfl_xor;  i=9 : p-pair
// table read from SMEM: stab[i*1024 + k*32 + lane] (conflict-free float2)
constexpr int FUSE_ITERS = 4;                       // rows per warp
constexpr int FUSE_SMEM = NCAP * 1024 * 8;          // 81920 B

__global__ __launch_bounds__(256) void fuse_kernel(
    const float* __restrict__ state,
    const float* __restrict__ br, const float* __restrict__ bg,
    const float* __restrict__ bc, float* __restrict__ out)
{
    extern __shared__ __align__(16) float2 stab[];  // NCAP*1024
    const int tid  = threadIdx.x;
    const int lane = tid & 31;
    const int w    = tid >> 5;

    // load table: 5120 float4, coalesced
    {
        const float4* src = reinterpret_cast<const float4*>(g_tab);
        float4* dst = reinterpret_cast<float4*>(stab);
        for (int i = tid; i < NCAP * 1024 / 2; i += 256) dst[i] = src[i];
    }
    __syncthreads();

    for (int it = 0; it < FUSE_ITERS; it++) {
        const int row = (blockIdx.x * FUSE_ITERS + it) * 8 + w;
        const float* st = state + (size_t)row * DOUT;

        float v[32];
#pragma unroll
        for (int e = 0; e < 16; e++) {
            float2 t = *reinterpret_cast<const float2*>(st + e * 64 + lane * 2);
            v[e * 2] = t.x; v[e * 2 + 1] = t.y;
        }

        // stages i = 0..3 (e-bit)
#pragma unroll
        for (int i = 0; i < 4; i++) {
            const int hb = 9 - i;
            const int eb = 1 << (hb - 6);
            const float2* tab = stab + i * 1024;
#pragma unroll
            for (int e = 0; e < 16; e++) {
                if (e & eb) continue;
#pragma unroll
                for (int p = 0; p < 2; p++) {
                    float2 cs = tab[(e * 2 + p) * 32 + lane];
                    float h0 = v[e * 2 + p], h1 = v[(e ^ eb) * 2 + p];
                    v[e * 2 + p]        = cs.x * h0 - cs.y * h1;
                    v[(e ^ eb) * 2 + p] = cs.y * h0 + cs.x * h1;
                }
            }
        }

        // stages i = 4..8 (lane-bit)
#pragma unroll
        for (int i = 4; i < 9; i++) {
            const int lm = 1 << (9 - i - 1);
            const bool up = (lane & lm) != 0;
            const float2* tab = stab + i * 1024;
#pragma unroll
            for (int k = 0; k < 32; k++) {
                float other = __shfl_xor_sync(0xffffffffu, v[k], lm);
                float2 cs = tab[k * 32 + lane];
                v[k] = up ? (cs.y * other + cs.x * v[k]) : (cs.x * v[k] - cs.y * other);
            }
        }

        // stage i = 9 (p-pair)
        {
            const float2* tab = stab + 9 * 1024;
#pragma unroll
            for (int e = 0; e < 16; e++) {
                float2 cs = tab[(e * 2) * 32 + lane];
                float h0 = v[e * 2], h1 = v[e * 2 + 1];
                v[e * 2]     = cs.x * h0 - cs.y * h1;
                v[e * 2 + 1] = cs.y * h0 + cs.x * h1;
            }
        }

        // gates + modReLU + output
        const __half* uxr = g_Ux + (size_t)row * 3072;
        const __half* srr = g_SR + (size_t)row * DOUT;
        const __half* sgr = g_SG + (size_t)row * DOUT;
        float* outr = out + (size_t)row * DOUT;

#pragma unroll
        for (int e = 0; e < 16; e++) {
            int j = e * 64 + lane * 2;
            float2 ucx = __half22float2(*reinterpret_cast<const __half2*>(uxr + j));
            float2 urx = __half22float2(*reinterpret_cast<const __half2*>(uxr + 1024 + j));
            float2 ugx = __half22float2(*reinterpret_cast<const __half2*>(uxr + 2048 + j));
            float2 srv = __half22float2(*reinterpret_cast<const __half2*>(srr + j));
            float2 sgv = __half22float2(*reinterpret_cast<const __half2*>(sgr + j));
            float2 stv = *reinterpret_cast<const float2*>(st + j);
            float2 brv = *reinterpret_cast<const float2*>(br + j);
            float2 bgv = *reinterpret_cast<const float2*>(bg + j);
            float2 bcv = *reinterpret_cast<const float2*>(bc + j);

            float2 o;
            {
                float rv = 1.0f / (1.0f + expf(-(urx.x + srv.x + brv.x)));
                float gv = 1.0f / (1.0f + expf(-(ugx.x + sgv.x + bgv.x)));
                float pre = rv * v[e * 2] + ucx.x;
                float mag = fabsf(pre) + 0.001f + bcv.x;
                float sgn = (pre > 0.0f) ? 1.0f : ((pre < 0.0f) ? -1.0f : 0.0f);
                o.x = gv * stv.x + (1.0f - gv) * (sgn * fmaxf(mag, 0.0f));
            }
            {
                float rv = 1.0f / (1.0f + expf(-(urx.y + srv.y + brv.y)));
                float gv = 1.0f / (1.0f + expf(-(ugx.y + sgv.y + bgv.y)));
                float pre = rv * v[e * 2 + 1] + ucx.y;
                float mag = fabsf(pre) + 0.001f + bcv.y;
                float sgn = (pre > 0.0f) ? 1.0f : ((pre < 0.0f) ? -1.0f : 0.0f);
                o.y = gv * stv.y + (1.0f - gv) * (sgn * fmaxf(mag, 0.0f));
            }
            *reinterpret_cast<float2*>(outr + j) = o;
        }
    }
}

// ---------------- launch ---------------------------------------------------
extern "C" void kernel_launch(void* const* d_in, const int* in_sizes, int n_in,
                              void* d_out, int out_size)
{
    const float* x     = (const float*)d_in[0];
    const float* state = (const float*)d_in[1];
    const float* theta = (const float*)d_in[2];
    const float* U     = (const float*)d_in[3];
    const float* W_r   = (const float*)d_in[4];
    const float* W_g   = (const float*)d_in[5];
    const float* br    = (const float*)d_in[6];
    const float* bg    = (const float*)d_in[7];
    const float* bc    = (const float*)d_in[8];
    float* out = (float*)d_out;

    __half *xh, *sh;
    cudaGetSymbolAddress((void**)&xh, g_xh);
    cudaGetSymbolAddress((void**)&sh, g_sh);

    static bool attr_done = false;
    if (!attr_done) {
        cudaFuncSetAttribute(gemm_mma, cudaFuncAttributeMaxDynamicSharedMemorySize, SMEM_SZ);
        cudaFuncSetAttribute(fuse_kernel, cudaFuncAttributeMaxDynamicSharedMemorySize, FUSE_SMEM);
        attr_done = true;
    }

    perm_kernel<<<NCAP, 1024>>>(theta);
    f2h_all<<<dim3(384, 5), 256>>>(x, state, U, W_r, W_g);
    gemm_mma<<<1280, 256, SMEM_SZ>>>(xh, sh);
    fuse_kernel<<<NROWS / (8 * FUSE_ITERS), 256, FUSE_SMEM>>>(state, br, bg, bc, out);
}